// round 16
// baseline (speedup 1.0000x reference)
#include <cuda_runtime.h>

// Fused coefficients: [ka0, kc0, ka1, kc1, bias]
__device__ float g_coef[5];

#define LAYERS 8
#define N_QUBITS 16

// The circuit has no entanglement and the 8 Rot layers are X-independent, so
// the whole network collapses per qubit to  ez(x) = A*cos(x) - C*sin(x), and
// only qubits 0,1 are read out. Thread q (q=0,1) composes the 8-layer Rot
// chain for qubit q into one 2x2 complex unitary, reduces it to (A, C), and
// folds in the linear head -> 5 scalars total.
__global__ void vqc_precompute_kernel(const float* __restrict__ params,
                                      const float* __restrict__ head_w,
                                      const float* __restrict__ head_b) {
    int q = threadIdx.x;
    if (q >= 2) return;

    float u00r = 1.f, u00i = 0.f, u01r = 0.f, u01i = 0.f;
    float u10r = 0.f, u10i = 0.f, u11r = 1.f, u11i = 0.f;

    #pragma unroll
    for (int l = 0; l < LAYERS; l++) {
        float phi   = params[l * (N_QUBITS * 3) + q * 3 + 0];
        float theta = params[l * (N_QUBITS * 3) + q * 3 + 1];
        float omega = params[l * (N_QUBITS * 3) + q * 3 + 2];
        float ct, st, cp, sp, cm, sm;
        __sincosf(0.5f * theta, &st, &ct);
        __sincosf(-0.5f * (phi + omega), &sp, &cp);
        __sincosf(0.5f * (phi - omega), &sm, &cm);
        // Rot(phi,theta,omega) = RZ(omega) RY(theta) RZ(phi)
        float m00r =  cp * ct, m00i =  sp * ct;
        float m01r = -cm * st, m01i = -sm * st;
        float m10r =  cm * st, m10i = -sm * st;
        float m11r =  cp * ct, m11i = -sp * ct;

        float n00r = m00r*u00r - m00i*u00i + m01r*u10r - m01i*u10i;
        float n00i = m00r*u00i + m00i*u00r + m01r*u10i + m01i*u10r;
        float n01r = m00r*u01r - m00i*u01i + m01r*u11r - m01i*u11i;
        float n01i = m00r*u01i + m00i*u01r + m01r*u11i + m01i*u11r;
        float n10r = m10r*u00r - m10i*u00i + m11r*u10r - m11i*u10i;
        float n10i = m10r*u00i + m10i*u00r + m11r*u10i + m11i*u10r;
        float n11r = m10r*u01r - m10i*u01i + m11r*u11r - m11i*u11i;
        float n11i = m10r*u01i + m10i*u01r + m11r*u11i + m11i*u11r;
        u00r = n00r; u00i = n00i; u01r = n01r; u01i = n01i;
        u10r = n10r; u10i = n10i; u11r = n11r; u11i = n11i;
    }

    float A = (u00r*u00r + u00i*u00i) - (u10r*u10r + u10i*u10i);
    float C = (u00i*u01r - u00r*u01i) - (u10i*u11r - u10r*u11i);

    float w = head_w[q];
    g_coef[q * 2 + 0] = w * A;
    g_coef[q * 2 + 1] = w * C;
    if (q == 0) g_coef[4] = head_b[0];
}

// Streaming kernel at the measured pattern floor: one thread per batch row,
// one L2-direct 8-byte load of the (x0,x1) row prefix, two fast sincos, one
// fused-FMA store. Mandatory DRAM traffic is 33.6 MB (64B granule per row +
// output); the measured best effective rate for this working set is
// ~3.88 TB/s across every load path / shape tried -> ~8.65 us floor.
__global__ void __launch_bounds__(256)
vqc_main_kernel(const float* __restrict__ X, float* __restrict__ out, int B) {
    int b = blockIdx.x * blockDim.x + threadIdx.x;
    if (b >= B) return;

    const float* p = X + (size_t)b * N_QUBITS;
    float x0, x1;
    asm volatile("ld.global.cg.v2.f32 {%0, %1}, [%2];"
                 : "=f"(x0), "=f"(x1) : "l"(p));

    float ka0 = g_coef[0], kc0 = g_coef[1];
    float ka1 = g_coef[2], kc1 = g_coef[3];
    float bias = g_coef[4];

    float s0, c0, s1, c1;
    __sincosf(x0, &s0, &c0);
    __sincosf(x1, &s1, &c1);

    out[b] = fmaf(ka0, c0, fmaf(-kc0, s0, fmaf(ka1, c1, fmaf(-kc1, s1, bias))));
}

extern "C" void kernel_launch(void* const* d_in, const int* in_sizes, int n_in,
                              void* d_out, int out_size) {
    const float* X      = (const float*)d_in[0];   // [B, 16]
    const float* params = (const float*)d_in[1];   // [8, 16, 3]
    const float* head_w = (const float*)d_in[2];   // [1, 2]
    const float* head_b = (const float*)d_in[3];   // [1]
    float* out = (float*)d_out;

    int B = in_sizes[0] / N_QUBITS;

    vqc_precompute_kernel<<<1, 32>>>(params, head_w, head_b);
    vqc_main_kernel<<<(B + 255) / 256, 256>>>(X, out, B);
}